// round 13
// baseline (speedup 1.0000x reference)
#include <cuda_runtime.h>
#include <cstdint>
#include <cstddef>

#define MD   28
#define D    784
#define SEQ  128
#define NCH  8            // chunks per batch
#define CLEN 16           // matrices per chunk
#define NW   4            // warps/block; warp w: chunk 2w (low half), 2w+1 (high half)
#define MAT_BYTES 3136
#define W_STRIDE  (4 * MAT_BYTES + 16)         // 16B pad kept (harmless)
#define SMEM_BYTES (NW * W_STRIDE)             // 50240 B

// ---------- packed f32x2 helpers ----------
__device__ __forceinline__ unsigned long long pack2(float lo, float hi) {
    unsigned long long r;
    asm("mov.b64 %0, {%1, %2};" : "=l"(r) : "f"(lo), "f"(hi));
    return r;
}
__device__ __forceinline__ void unpack2(unsigned long long v, float& lo, float& hi) {
    asm("mov.b64 {%0, %1}, %2;" : "=f"(lo), "=f"(hi) : "l"(v));
}
__device__ __forceinline__ unsigned long long mul2(unsigned long long a, unsigned long long b) {
    unsigned long long r;
    asm("mul.rn.f32x2 %0, %1, %2;" : "=l"(r) : "l"(a), "l"(b));
    return r;
}
__device__ __forceinline__ void fma2(unsigned long long& d, unsigned long long a, unsigned long long b) {
    asm("fma.rn.f32x2 %0, %1, %2, %0;" : "+l"(d) : "l"(a), "l"(b));
}

// ---------- TMA bulk-copy + mbarrier helpers ----------
__device__ __forceinline__ unsigned s2u(const void* p) {
    return (unsigned)__cvta_generic_to_shared(p);
}
__device__ __forceinline__ void mbar_init(void* mbar) {
    asm volatile("mbarrier.init.shared.b64 [%0], %1;"
                 :: "r"(s2u(mbar)), "r"(1u) : "memory");
}
__device__ __forceinline__ void mbar_expect_tx(void* mbar, unsigned bytes) {
    asm volatile("mbarrier.arrive.expect_tx.shared.b64 _, [%0], %1;"
                 :: "r"(s2u(mbar)), "r"(bytes) : "memory");
}
__device__ __forceinline__ void mbar_wait(void* mbar, unsigned parity) {
    asm volatile(
        "{\n\t"
        ".reg .pred P;\n"
        "W%=:\n\t"
        "mbarrier.try_wait.parity.acquire.cta.shared::cta.b64 P, [%0], %1, 0x989680;\n\t"
        "@P bra D%=;\n\t"
        "bra W%=;\n"
        "D%=:\n\t"
        "}"
        :: "r"(s2u(mbar)), "r"(parity) : "memory");
}
__device__ __forceinline__ void bulk_cp(void* dst_smem, const void* src_gmem,
                                        unsigned bytes, void* mbar) {
    asm volatile(
        "cp.async.bulk.shared::cta.global.mbarrier::complete_tx::bytes [%0], [%1], %2, [%3];"
        :: "r"(s2u(dst_smem)), "l"(src_gmem), "r"(bytes), "r"(s2u(mbar)) : "memory");
}
__device__ __forceinline__ void fence_proxy_async_cta() {
    asm volatile("fence.proxy.async.shared::cta;" ::: "memory");
}

// Two rows per lane, W in smem. Explicit 4-quad rolling prefetch window:
// quad t+4 is loaded BEFORE the FMAs of quad t, guaranteeing ~32 issue-cycles
// of cover for the 29-cycle LDS latency regardless of ptxas scheduling.
__device__ __forceinline__ void mm_step2(float c0[MD], float c1[MD],
                                         const float4* __restrict__ w) {
    unsigned long long a0[14], a1[14];
    float4 win[4];
    #pragma unroll
    for (int t = 0; t < 4; ++t) win[t] = w[t];

    #pragma unroll
    for (int k = 0; k < MD; ++k) {
        unsigned long long k0 = pack2(c0[k], c0[k]);
        unsigned long long k1 = pack2(c1[k], c1[k]);
        #pragma unroll
        for (int q = 0; q < 7; ++q) {
            const int t = k * 7 + q;
            float4 wv = win[t & 3];
            if (t + 4 < 196) win[t & 3] = w[t + 4];   // prefetch 4 quads ahead
            unsigned long long wlo = pack2(wv.x, wv.y);
            unsigned long long whi = pack2(wv.z, wv.w);
            if (k == 0) {
                a0[2*q]   = mul2(k0, wlo);
                a0[2*q+1] = mul2(k0, whi);
                a1[2*q]   = mul2(k1, wlo);
                a1[2*q+1] = mul2(k1, whi);
            } else {
                fma2(a0[2*q],   k0, wlo);
                fma2(a0[2*q+1], k0, whi);
                fma2(a1[2*q],   k1, wlo);
                fma2(a1[2*q+1], k1, whi);
            }
        }
    }
    #pragma unroll
    for (int q = 0; q < 14; ++q) {
        unpack2(a0[q], c0[2*q], c0[2*q+1]);
        unpack2(a1[q], c1[2*q], c1[2*q+1]);
    }
}

// store both rows of one lane into a 28x28 float tile
__device__ __forceinline__ void store2(float* tile, int r0, int r1,
                                       const float c0[MD], const float c1[MD]) {
    float4* p0 = (float4*)(tile + r0 * MD);
    float4* p1 = (float4*)(tile + r1 * MD);
    #pragma unroll
    for (int q = 0; q < 7; ++q) {
        p0[q] = make_float4(c0[4*q], c0[4*q+1], c0[4*q+2], c0[4*q+3]);
        p1[q] = make_float4(c1[4*q], c1[4*q+1], c1[4*q+2], c1[4*q+3]);
    }
}

// One block = one batch. Warp w runs chunks 2w (lanes 0-15) and 2w+1 (lanes 16-31),
// 2 rows per lane, per-chain TMA double buffers; 7-matmul combine tree.
__global__ void __launch_bounds__(NW * 32, 3)
w2m_fused(const int* __restrict__ sent, const float* __restrict__ tab,
          float* __restrict__ out)
{
    extern __shared__ char smem_raw[];
    __shared__ __align__(8) unsigned long long mbar[NW][2];

    int b    = blockIdx.x;
    int w    = (int)(threadIdx.x >> 5);
    int lane = (int)(threadIdx.x & 31);
    int h    = lane >> 4;
    int sl   = lane & 15;
    int act  = (sl < 14);
    int r0   = act ? sl : 0;
    int r1   = act ? sl + 14 : 0;

    char* wbase = smem_raw + (size_t)w * W_STRIDE;
    float4* bufA0 = (float4*)(wbase);
    float4* bufA1 = (float4*)(wbase + MAT_BYTES);
    float4* bufB0 = (float4*)(wbase + 2 * MAT_BYTES + 16);
    float4* bufB1 = (float4*)(wbase + 3 * MAT_BYTES + 16);
    auto slot = [&](int ww, int hh) -> float* {
        return (float*)(smem_raw + (size_t)ww * W_STRIDE
                        + (hh ? (2 * MAT_BYTES + 16) : 0));
    };

    if (lane == 0) {
        mbar_init(&mbar[w][0]);
        mbar_init(&mbar[w][1]);
        fence_proxy_async_cta();
    }
    __syncwarp();

    int iA = sent[b * SEQ + (2 * w)     * CLEN + sl];
    int iB = sent[b * SEQ + (2 * w + 1) * CLEN + sl];

    {
        int a1i = __shfl_sync(0xffffffffu, iA, 1);
        int b1i = __shfl_sync(0xffffffffu, iB, 1);
        if (lane == 0) {
            mbar_expect_tx(&mbar[w][1], 2 * MAT_BYTES);
            bulk_cp(bufA1, tab + (size_t)a1i * D, MAT_BYTES, &mbar[w][1]);
            bulk_cp(bufB1, tab + (size_t)b1i * D, MAT_BYTES, &mbar[w][1]);
        }
    }

    float c0[MD], c1[MD];
    {
        int a0i = __shfl_sync(0xffffffffu, iA, 0);
        int b0i = __shfl_sync(0xffffffffu, iB, 0);
        int i0  = h ? b0i : a0i;
        const float4* w0 = (const float4*)(tab + (size_t)i0 * D);
        #pragma unroll
        for (int q = 0; q < 7; ++q) {
            float4 v0 = __ldg(w0 + r0 * 7 + q);
            float4 v1 = __ldg(w0 + r1 * 7 + q);
            c0[4*q] = v0.x; c0[4*q+1] = v0.y; c0[4*q+2] = v0.z; c0[4*q+3] = v0.w;
            c1[4*q] = v1.x; c1[4*q+1] = v1.y; c1[4*q+2] = v1.z; c1[4*q+3] = v1.w;
        }
    }

    unsigned ph0 = 0, ph1 = 0;

    #pragma unroll 1
    for (int s = 1; s < CLEN; ++s) {
        if (s + 1 < CLEN) {
            int an = __shfl_sync(0xffffffffu, iA, s + 1);
            int bn = __shfl_sync(0xffffffffu, iB, s + 1);
            if (lane == 0) {
                int st = (s + 1) & 1;
                void* mb = &mbar[w][st];
                mbar_expect_tx(mb, 2 * MAT_BYTES);
                bulk_cp(st ? bufA1 : bufA0, tab + (size_t)an * D, MAT_BYTES, mb);
                bulk_cp(st ? bufB1 : bufB0, tab + (size_t)bn * D, MAT_BYTES, mb);
            }
        }
        if (s & 1) { mbar_wait(&mbar[w][1], ph1); ph1 ^= 1u; }
        else       { mbar_wait(&mbar[w][0], ph0); ph0 ^= 1u; }
        const float4* wp = (s & 1) ? (h ? bufB1 : bufA1) : (h ? bufB0 : bufA0);
        mm_step2(c0, c1, wp);
    }

    // ---- combine tree: 8 partials -> 1 ----
    if (h == 1 && act) store2(slot(w, 1), r0, r1, c0, c1);
    __syncthreads();

    // level 1: Q_w = P_{2w} * P_{2w+1}
    mm_step2(c0, c1, (const float4*)slot(w, 1));
    if (h == 0 && act && (w == 1 || w == 3)) store2(slot(w, 0), r0, r1, c0, c1);
    __syncthreads();

    // level 2: R0 = Q0*Q1 (warp 0), R1 = Q2*Q3 (warp 2)
    if (w == 0) {
        mm_step2(c0, c1, (const float4*)slot(1, 0));
    } else if (w == 2) {
        mm_step2(c0, c1, (const float4*)slot(3, 0));
        if (h == 0 && act) store2(slot(2, 0), r0, r1, c0, c1);
    }
    __syncthreads();

    // level 3: out = R0 * R1 (warp 0, low half writes)
    if (w == 0) {
        mm_step2(c0, c1, (const float4*)slot(2, 0));
        if (h == 0 && act)
            store2(out + (size_t)b * D, r0, r1, c0, c1);
    }
}

extern "C" void kernel_launch(void* const* d_in, const int* in_sizes, int n_in,
                              void* d_out, int out_size)
{
    const int*   sent;
    const float* tab;
    if (in_sizes[0] < in_sizes[1]) {
        sent = (const int*)d_in[0];
        tab  = (const float*)d_in[1];
    } else {
        sent = (const int*)d_in[1];
        tab  = (const float*)d_in[0];
    }
    int B = out_size / D;   // 512

    static int smem_set = 0;
    if (!smem_set) {
        cudaFuncSetAttribute(w2m_fused,
                             cudaFuncAttributeMaxDynamicSharedMemorySize, SMEM_BYTES);
        smem_set = 1;
    }

    w2m_fused<<<B, NW * 32, SMEM_BYTES>>>(sent, tab, (float*)d_out);
}

// round 14
// speedup vs baseline: 1.0241x; 1.0241x over previous
#include <cuda_runtime.h>
#include <cstdint>
#include <cstddef>

#define MD   28
#define D    784
#define SEQ  128
#define NWB  3            // warps per block; 2 chains each -> 6 chunks
#define MAT_BYTES 3136
#define W_STRIDE  (4 * MAT_BYTES + 16)     // A0,A1,[pad],B0,B1 per warp
#define SMEM_BYTES (NWB * W_STRIDE)        // 37680 B

// ---------- packed f32x2 helpers ----------
__device__ __forceinline__ unsigned long long pack2(float lo, float hi) {
    unsigned long long r;
    asm("mov.b64 %0, {%1, %2};" : "=l"(r) : "f"(lo), "f"(hi));
    return r;
}
__device__ __forceinline__ void unpack2(unsigned long long v, float& lo, float& hi) {
    asm("mov.b64 {%0, %1}, %2;" : "=f"(lo), "=f"(hi) : "l"(v));
}
__device__ __forceinline__ unsigned long long mul2(unsigned long long a, unsigned long long b) {
    unsigned long long r;
    asm("mul.rn.f32x2 %0, %1, %2;" : "=l"(r) : "l"(a), "l"(b));
    return r;
}
__device__ __forceinline__ void fma2(unsigned long long& d, unsigned long long a, unsigned long long b) {
    asm("fma.rn.f32x2 %0, %1, %2, %0;" : "+l"(d) : "l"(a), "l"(b));
}

// ---------- TMA bulk-copy + mbarrier helpers ----------
__device__ __forceinline__ unsigned s2u(const void* p) {
    return (unsigned)__cvta_generic_to_shared(p);
}
__device__ __forceinline__ void mbar_init(void* mbar) {
    asm volatile("mbarrier.init.shared.b64 [%0], %1;"
                 :: "r"(s2u(mbar)), "r"(1u) : "memory");
}
__device__ __forceinline__ void mbar_expect_tx(void* mbar, unsigned bytes) {
    asm volatile("mbarrier.arrive.expect_tx.shared.b64 _, [%0], %1;"
                 :: "r"(s2u(mbar)), "r"(bytes) : "memory");
}
__device__ __forceinline__ void mbar_wait(void* mbar, unsigned parity) {
    asm volatile(
        "{\n\t"
        ".reg .pred P;\n"
        "W%=:\n\t"
        "mbarrier.try_wait.parity.acquire.cta.shared::cta.b64 P, [%0], %1, 0x989680;\n\t"
        "@P bra D%=;\n\t"
        "bra W%=;\n"
        "D%=:\n\t"
        "}"
        :: "r"(s2u(mbar)), "r"(parity) : "memory");
}
__device__ __forceinline__ void bulk_cp(void* dst_smem, const void* src_gmem,
                                        unsigned bytes, void* mbar) {
    asm volatile(
        "cp.async.bulk.shared::cta.global.mbarrier::complete_tx::bytes [%0], [%1], %2, [%3];"
        :: "r"(s2u(dst_smem)), "l"(src_gmem), "r"(bytes), "r"(s2u(mbar)) : "memory");
}
__device__ __forceinline__ void fence_proxy_async_cta() {
    asm volatile("fence.proxy.async.shared::cta;" ::: "memory");
}

// Two rows per lane: {c0,c1} = rows sl, sl+14 of the running product.
// W in smem; the two 16-lane halves may pass different pointers (dual broadcast).
__device__ __forceinline__ void mm_step2(float c0[MD], float c1[MD],
                                         const float4* __restrict__ w) {
    unsigned long long a0[14], a1[14];
    #pragma unroll
    for (int k = 0; k < MD; ++k) {
        unsigned long long k0 = pack2(c0[k], c0[k]);
        unsigned long long k1 = pack2(c1[k], c1[k]);
        #pragma unroll
        for (int q = 0; q < 7; ++q) {
            float4 wv = w[k * 7 + q];
            unsigned long long wlo = pack2(wv.x, wv.y);
            unsigned long long whi = pack2(wv.z, wv.w);
            if (k == 0) {
                a0[2*q]   = mul2(k0, wlo);
                a0[2*q+1] = mul2(k0, whi);
                a1[2*q]   = mul2(k1, wlo);
                a1[2*q+1] = mul2(k1, whi);
            } else {
                fma2(a0[2*q],   k0, wlo);
                fma2(a0[2*q+1], k0, whi);
                fma2(a1[2*q],   k1, wlo);
                fma2(a1[2*q+1], k1, whi);
            }
        }
    }
    #pragma unroll
    for (int q = 0; q < 14; ++q) {
        unpack2(a0[q], c0[2*q], c0[2*q+1]);
        unpack2(a1[q], c1[2*q], c1[2*q+1]);
    }
}

__device__ __forceinline__ void store2(float* tile, int r0, int r1,
                                       const float c0[MD], const float c1[MD]) {
    float4* p0 = (float4*)(tile + r0 * MD);
    float4* p1 = (float4*)(tile + r1 * MD);
    #pragma unroll
    for (int q = 0; q < 7; ++q) {
        p0[q] = make_float4(c0[4*q], c0[4*q+1], c0[4*q+2], c0[4*q+3]);
        p1[q] = make_float4(c1[4*q], c1[4*q+1], c1[4*q+2], c1[4*q+3]);
    }
}

// One block = one batch, 3 warps. Warp w runs two equal chains:
//   w0: steps [0,22) and [22,44)    (len 22)
//   w1: steps [44,65) and [65,86)   (len 21)
//   w2: steps [86,107) and [107,128)(len 21)
// Tree: Qw = PA*PB per warp (warp-local), then warp0: out = Q0*Q1*Q2.
__global__ void __launch_bounds__(NWB * 32, 4)
w2m_fused(const int* __restrict__ sent, const float* __restrict__ tab,
          float* __restrict__ out)
{
    extern __shared__ char smem_raw[];
    __shared__ __align__(8) unsigned long long mbar[NWB][2];

    int b    = blockIdx.x;
    int w    = (int)(threadIdx.x >> 5);
    int lane = (int)(threadIdx.x & 31);
    int h    = lane >> 4;                 // 0 -> chain A, 1 -> chain B
    int sl   = lane & 15;
    int act  = (sl < 14);
    int r0   = act ? sl : 0;
    int r1   = act ? sl + 14 : 0;

    int clen   = (w == 0) ? 22 : 21;
    int startA = (w == 0) ? 0 : ((w == 1) ? 44 : 86);
    int startB = startA + clen;

    char* wbase = smem_raw + (size_t)w * W_STRIDE;
    float4* bufA0 = (float4*)(wbase);
    float4* bufA1 = (float4*)(wbase + MAT_BYTES);
    float4* bufB0 = (float4*)(wbase + 2 * MAT_BYTES + 16);
    float4* bufB1 = (float4*)(wbase + 3 * MAT_BYTES + 16);
    auto warpA0 = [&](int ww) -> float* {       // Q-slot of warp ww
        return (float*)(smem_raw + (size_t)ww * W_STRIDE);
    };

    if (lane == 0) {
        mbar_init(&mbar[w][0]);
        mbar_init(&mbar[w][1]);
        fence_proxy_async_cta();
    }
    __syncwarp();

    // full-lane index storage: lane l (0..clen-1) holds step-l index of each chain
    int la = (lane < clen) ? lane : 0;
    int iA = sent[b * SEQ + startA + la];
    int iB = sent[b * SEQ + startB + la];

    // kick off TMA for step 1 of both chains into stage 1
    {
        int a1i = __shfl_sync(0xffffffffu, iA, 1);
        int b1i = __shfl_sync(0xffffffffu, iB, 1);
        if (lane == 0) {
            mbar_expect_tx(&mbar[w][1], 2 * MAT_BYTES);
            bulk_cp(bufA1, tab + (size_t)a1i * D, MAT_BYTES, &mbar[w][1]);
            bulk_cp(bufB1, tab + (size_t)b1i * D, MAT_BYTES, &mbar[w][1]);
        }
    }

    // c = rows r0,r1 of matrix 0 of this half's chain
    float c0[MD], c1[MD];
    {
        int a0i = __shfl_sync(0xffffffffu, iA, 0);
        int b0i = __shfl_sync(0xffffffffu, iB, 0);
        int i0  = h ? b0i : a0i;
        const float4* w0 = (const float4*)(tab + (size_t)i0 * D);
        #pragma unroll
        for (int q = 0; q < 7; ++q) {
            float4 v0 = __ldg(w0 + r0 * 7 + q);
            float4 v1 = __ldg(w0 + r1 * 7 + q);
            c0[4*q] = v0.x; c0[4*q+1] = v0.y; c0[4*q+2] = v0.z; c0[4*q+3] = v0.w;
            c1[4*q] = v1.x; c1[4*q+1] = v1.y; c1[4*q+2] = v1.z; c1[4*q+3] = v1.w;
        }
    }

    unsigned ph0 = 0, ph1 = 0;

    #pragma unroll 1
    for (int s = 1; s < clen; ++s) {
        if (s + 1 < clen) {
            int an = __shfl_sync(0xffffffffu, iA, s + 1);
            int bn = __shfl_sync(0xffffffffu, iB, s + 1);
            if (lane == 0) {
                int st = (s + 1) & 1;
                void* mb = &mbar[w][st];
                mbar_expect_tx(mb, 2 * MAT_BYTES);
                bulk_cp(st ? bufA1 : bufA0, tab + (size_t)an * D, MAT_BYTES, mb);
                bulk_cp(st ? bufB1 : bufB0, tab + (size_t)bn * D, MAT_BYTES, mb);
            }
        }
        if (s & 1) { mbar_wait(&mbar[w][1], ph1); ph1 ^= 1u; }
        else       { mbar_wait(&mbar[w][0], ph0); ph0 ^= 1u; }
        const float4* wp = (s & 1) ? (h ? bufB1 : bufA1) : (h ? bufB0 : bufA0);
        mm_step2(c0, c1, wp);
    }

    // ---- level 1 (warp-local): Q_w = P_A * P_B ----
    if (h == 1 && act) store2((float*)bufB0, r0, r1, c0, c1);   // P_B matrix
    __syncwarp();
    mm_step2(c0, c1, bufB0);                                    // h=0 lanes: Q_w

    // warps 1,2 publish Q; single block barrier
    if (w > 0 && h == 0 && act) store2(warpA0(w), r0, r1, c0, c1);
    __syncthreads();

    // ---- warp 0: out = Q0 * Q1 * Q2 ----
    if (w == 0) {
        mm_step2(c0, c1, (const float4*)warpA0(1));
        mm_step2(c0, c1, (const float4*)warpA0(2));
        if (h == 0 && act)
            store2(out + (size_t)b * D, r0, r1, c0, c1);
    }
}

extern "C" void kernel_launch(void* const* d_in, const int* in_sizes, int n_in,
                              void* d_out, int out_size)
{
    const int*   sent;
    const float* tab;
    if (in_sizes[0] < in_sizes[1]) {
        sent = (const int*)d_in[0];
        tab  = (const float*)d_in[1];
    } else {
        sent = (const int*)d_in[1];
        tab  = (const float*)d_in[0];
    }
    int B = out_size / D;   // 512

    static int smem_set = 0;
    if (!smem_set) {
        cudaFuncSetAttribute(w2m_fused,
                             cudaFuncAttributeMaxDynamicSharedMemorySize, SMEM_BYTES);
        smem_set = 1;
    }

    w2m_fused<<<B, NWB * 32, SMEM_BYTES>>>(sent, tab, (float*)d_out);
}